// round 12
// baseline (speedup 1.0000x reference)
#include <cuda_runtime.h>
#include <cuda_bf16.h>
#include <cstdint>

// LJ constants (match reference); sigma=1, cutoff=5
#define EPSILON 1.0f
#define SHIFT_F (4.0f * (1.0f/244140625.0f - 1.0f/15625.0f))

// Replicated accumulation scratch, L2-resident (3.2 MB static).
// Contention ladder (edge time): NREP=1 ~85us, NREP=4 ~73us, NREP>=8 ~70us.
#define NREP 8
#define MAX_ATOMS 100000
#define REP_STRIDE (MAX_ATOMS + 128)
__device__ __align__(16) float g_scratch[NREP * REP_STRIDE];

// Ticket counters for fused tail-reduce. Zero-init at load; reset by the
// last reduce block every call -> zero at entry to every launch/replay.
__device__ unsigned g_ticket;
__device__ unsigned g_done;

__device__ __forceinline__ float lj_half_e(float x, float y, float z) {
    float r2   = fmaf(x, x, fmaf(y, y, z * z));
    float inv2 = 1.0f / r2;
    float sr6  = inv2 * inv2 * inv2;
    float e    = 4.0f * EPSILON * fmaf(sr6, sr6, -sr6) - SHIFT_F;
    return 0.5f * e;
}

// Edge kernel with fused tail-reduce.
// Phase 1 (all blocks): 1 edge/thread, replica-spread fire-and-forget REDs.
// Phase 2 (last R tickets): spin until all blocks ticketed (=> all REDs
// fenced & posted to L2), then reduce one 256-atom slice -> out.
__global__ void __launch_bounds__(256)
lj_edge_fused(const float* __restrict__ dist,
              const int* __restrict__ atom_a,
              const int* __restrict__ atom_b,
              float* __restrict__ out,
              int n_edges, int n_atoms, int n_red_blocks) {
    int i = blockIdx.x * blockDim.x + threadIdx.x;

    if (i < n_edges) {
        float x = dist[3 * i + 0];
        float y = dist[3 * i + 1];
        float z = dist[3 * i + 2];
        float h = lj_half_e(x, y, z);

        int ia = atom_a[i];
        int ib = atom_b[i];

        float* rep = g_scratch + (i & (NREP - 1)) * REP_STRIDE;
        atomicAdd(rep + ia, h);   // RED.ADD, fire-and-forget
        atomicAdd(rep + ib, h);
    }

    // Make this block's REDs visible before announcing completion.
    __threadfence();
    __syncthreads();

    __shared__ unsigned s_ticket;
    if (threadIdx.x == 0)
        s_ticket = atomicAdd(&g_ticket, 1u);   // ticket = #blocks completed
    __syncthreads();

    unsigned G = gridDim.x;
    unsigned first_red = G - (unsigned)n_red_blocks;
    unsigned t = s_ticket;
    if (t < first_red) return;                 // pure edge block: done

    // Reduce block: slice id by ticket VALUE -> deterministic output.
    int slice = (int)(t - first_red);

    // Wait until every block has ticketed (all REDs globally visible).
    if (threadIdx.x == 0) {
        volatile unsigned* vt = &g_ticket;
        while (*vt < G) { __nanosleep(64); }
    }
    __syncthreads();

    int atom = slice * 256 + threadIdx.x;
    if (atom < n_atoms) {
        float s = 0.0f;
        #pragma unroll
        for (int r = 0; r < NREP; r++)
            s += __ldcg(&g_scratch[r * REP_STRIDE + atom]);  // L2 read
        out[atom] = s;
    }

    // Reset counters for the next launch/replay (invariant: zero at entry).
    __syncthreads();
    if (threadIdx.x == 0) {
        unsigned d = atomicAdd(&g_done, 1u);
        if (d == (unsigned)n_red_blocks - 1u) {
            g_ticket = 0u;
            g_done   = 0u;
            __threadfence();
        }
    }
}

// Backup zero kernel in case symbol lookup ever fails.
__global__ void __launch_bounds__(256)
lj_zero_scratch_v4(int n_vec4) {
    int i = blockIdx.x * blockDim.x + threadIdx.x;
    if (i < n_vec4)
        reinterpret_cast<float4*>(g_scratch)[i] = make_float4(0.f, 0.f, 0.f, 0.f);
}

// Fallback (atom count exceeds static scratch): direct atomics.
__global__ void lj_zero_out(float* __restrict__ out, int n) {
    int i = blockIdx.x * blockDim.x + threadIdx.x;
    if (i < n) out[i] = 0.0f;
}
__global__ void lj_edge_kernel_direct(const float* __restrict__ dist,
                                      const int* __restrict__ atom_a,
                                      const int* __restrict__ atom_b,
                                      float* __restrict__ out,
                                      int n_edges) {
    int i = blockIdx.x * blockDim.x + threadIdx.x;
    if (i >= n_edges) return;
    float h = lj_half_e(dist[3*i], dist[3*i+1], dist[3*i+2]);
    atomicAdd(out + atom_a[i], h);
    atomicAdd(out + atom_b[i], h);
}

extern "C" void kernel_launch(void* const* d_in, const int* in_sizes, int n_in,
                              void* d_out, int out_size) {
    const float* dist   = (const float*)d_in[0];
    const int*   atom_a = (const int*)d_in[1];   // JAX x64-disabled: int32
    const int*   atom_b = (const int*)d_in[2];
    float* out = (float*)d_out;

    int n_edges = in_sizes[1];
    int n_atoms = out_size;
    const int T = 256;

    int edge_blocks = (n_edges + T - 1) / T;
    int red_blocks  = (n_atoms + T - 1) / T;

    if (n_atoms <= MAX_ATOMS && edge_blocks >= 2 * red_blocks) {
        // Zero scratch via memset node (beats the latency-bound zero kernel).
        void* scratch_ptr = nullptr;
        cudaError_t e = cudaGetSymbolAddress(&scratch_ptr, g_scratch);
        if (e == cudaSuccess && scratch_ptr != nullptr) {
            cudaMemsetAsync(scratch_ptr, 0, sizeof(float) * NREP * REP_STRIDE, 0);
        } else {
            int n_vec4 = (NREP * REP_STRIDE) / 4;
            lj_zero_scratch_v4<<<(n_vec4 + T - 1) / T, T>>>(n_vec4);
        }

        lj_edge_fused<<<edge_blocks, T>>>(dist, atom_a, atom_b, out,
                                          n_edges, n_atoms, red_blocks);
    } else {
        lj_zero_out<<<(n_atoms + T - 1) / T, T>>>(out, n_atoms);
        lj_edge_kernel_direct<<<edge_blocks, T>>>(dist, atom_a, atom_b, out, n_edges);
    }
}

// round 13
// speedup vs baseline: 1.5887x; 1.5887x over previous
#include <cuda_runtime.h>
#include <cuda_bf16.h>
#include <cstdint>

// LJ constants (match reference); sigma=1, cutoff=5
#define EPSILON 1.0f
#define SHIFT_F (4.0f * (1.0f/244140625.0f - 1.0f/15625.0f))

// Replicated accumulation scratch, fully L2-resident (3.2 MB static).
// Contention ladder (edge-kernel time): NREP=1 ~85us, NREP=4 ~73us,
// NREP=8/16/32 ~70us flat. NREP=8 is the knee.
//
// Structure is load-bearing: memset -> edge -> reduce as 3 independent
// graph nodes. Both fusion attempts (R8 clear-in-reduce, R12 ticketed
// tail-reduce) regressed 25-45us: any fence/ordering imposed on the RED
// stream collapses its MLP at the LTS.
#define NREP 8
#define MAX_ATOMS 100000
#define REP_STRIDE (MAX_ATOMS + 128)
__device__ __align__(16) float g_scratch[NREP * REP_STRIDE];

__device__ __forceinline__ float lj_half_e(float x, float y, float z) {
    float r2   = fmaf(x, x, fmaf(y, y, z * z));
    float inv2 = 1.0f / r2;
    float sr6  = inv2 * inv2 * inv2;
    float e    = 4.0f * EPSILON * fmaf(sr6, sr6, -sr6) - SHIFT_F;
    return 0.5f * e;
}

// Scalar 1-edge/thread; REDG/LTS-atomic-bound at ~70us (12.8M fp32 REDs,
// ~70K ops/LTS-slice x ~2cyc) — invariant across 5 instruction-mix
// variants. Replica index warp-uniform so the base lives in the uniform
// datapath (one UR computation/warp instead of per-lane IMAD).
__global__ void __launch_bounds__(256)
lj_edge_kernel_rep(const float* __restrict__ dist,
                   const int* __restrict__ atom_a,
                   const int* __restrict__ atom_b,
                   int n_edges) {
    int i = blockIdx.x * blockDim.x + threadIdx.x;
    if (i >= n_edges) return;

    float x = dist[3 * i + 0];
    float y = dist[3 * i + 1];
    float z = dist[3 * i + 2];
    float h = lj_half_e(x, y, z);

    int ia = atom_a[i];
    int ib = atom_b[i];

    // warp-uniform replica: (global warp id) & 7
    float* rep = g_scratch + ((i >> 5) & (NREP - 1)) * REP_STRIDE;
    atomicAdd(rep + ia, h);   // RED.ADD, fire-and-forget
    atomicAdd(rep + ib, h);
}

// Reduce NREP replicas -> out, 1 atom/thread (391 blocks; measured at the
// launch-ramp floor ~4.8us, invariant to per-thread work shape).
__global__ void __launch_bounds__(256)
lj_reduce_kernel_s(float* __restrict__ out, int n_atoms) {
    int i = blockIdx.x * blockDim.x + threadIdx.x;
    if (i >= n_atoms) return;

    float s = 0.0f;
    #pragma unroll
    for (int r = 0; r < NREP; r++)
        s += g_scratch[r * REP_STRIDE + i];
    out[i] = s;
}

// Fallback kernels (atom count exceeds static scratch): direct atomics.
__global__ void lj_zero_out(float* __restrict__ out, int n) {
    int i = blockIdx.x * blockDim.x + threadIdx.x;
    if (i < n) out[i] = 0.0f;
}
__global__ void lj_edge_kernel_direct(const float* __restrict__ dist,
                                      const int* __restrict__ atom_a,
                                      const int* __restrict__ atom_b,
                                      float* __restrict__ out,
                                      int n_edges) {
    int i = blockIdx.x * blockDim.x + threadIdx.x;
    if (i >= n_edges) return;
    float h = lj_half_e(dist[3*i], dist[3*i+1], dist[3*i+2]);
    atomicAdd(out + atom_a[i], h);
    atomicAdd(out + atom_b[i], h);
}

// Backup zero kernel in case symbol lookup ever fails.
__global__ void __launch_bounds__(256)
lj_zero_scratch_v4(int n_vec4) {
    int i = blockIdx.x * blockDim.x + threadIdx.x;
    if (i < n_vec4)
        reinterpret_cast<float4*>(g_scratch)[i] = make_float4(0.f, 0.f, 0.f, 0.f);
}

extern "C" void kernel_launch(void* const* d_in, const int* in_sizes, int n_in,
                              void* d_out, int out_size) {
    const float* dist   = (const float*)d_in[0];
    const int*   atom_a = (const int*)d_in[1];   // JAX x64-disabled: int32
    const int*   atom_b = (const int*)d_in[2];
    float* out = (float*)d_out;

    int n_edges = in_sizes[1];
    int n_atoms = out_size;
    const int T = 256;

    if (n_atoms <= MAX_ATOMS) {
        // Zero scratch via memset node (measured: beats the 4.3-4.6us
        // latency-bound zero kernel).
        void* scratch_ptr = nullptr;
        cudaError_t e = cudaGetSymbolAddress(&scratch_ptr, g_scratch);
        if (e == cudaSuccess && scratch_ptr != nullptr) {
            cudaMemsetAsync(scratch_ptr, 0, sizeof(float) * NREP * REP_STRIDE, 0);
        } else {
            int n_vec4 = (NREP * REP_STRIDE) / 4;
            lj_zero_scratch_v4<<<(n_vec4 + T - 1) / T, T>>>(n_vec4);
        }

        lj_edge_kernel_rep<<<(n_edges + T - 1) / T, T>>>(dist, atom_a, atom_b, n_edges);
        lj_reduce_kernel_s<<<(n_atoms + T - 1) / T, T>>>(out, n_atoms);
    } else {
        lj_zero_out<<<(n_atoms + T - 1) / T, T>>>(out, n_atoms);
        lj_edge_kernel_direct<<<(n_edges + T - 1) / T, T>>>(dist, atom_a, atom_b, out, n_edges);
    }
}

// round 16
// speedup vs baseline: 1.6075x; 1.0119x over previous
#include <cuda_runtime.h>
#include <cuda_bf16.h>
#include <cstdint>

// LJ constants (match reference); sigma=1, cutoff=5
#define EPSILON 1.0f
#define SHIFT_F (4.0f * (1.0f/244140625.0f - 1.0f/15625.0f))

// Replicated accumulation scratch, fully L2-resident (3.2 MB static).
// Contention ladder (edge-kernel time): NREP=1 ~85us, NREP=4 ~73us,
// NREP=8/16/32 ~70us flat. NREP=8 is the knee.
//
// Structure is load-bearing: memset -> edge -> reduce as 3 independent
// graph nodes. Both fusion attempts (R8, R12) regressed 25-45us: any
// fence/ordering imposed on the RED stream collapses its MLP at the LTS.
#define NREP 8
#define MAX_ATOMS 100000
#define REP_STRIDE (MAX_ATOMS + 128)
__device__ __align__(16) float g_scratch[NREP * REP_STRIDE];

__device__ __forceinline__ float lj_half_e(float x, float y, float z) {
    float r2   = fmaf(x, x, fmaf(y, y, z * z));
    float inv2 = 1.0f / r2;
    float sr6  = inv2 * inv2 * inv2;
    float e    = 4.0f * EPSILON * fmaf(sr6, sr6, -sr6) - SHIFT_F;
    return 0.5f * e;
}

// Scalar 1-edge/thread; REDG/LTS-atomic-bound at ~70us — invariant across
// 5 instruction-mix variants. NEW: all input loads use __ldcs (evict-first
// streaming) so the 128MB one-touch stream doesn't evict the 3.2MB scratch
// from L2 (R13 profile showed the reduce re-reading scratch from DRAM).
__global__ void __launch_bounds__(256)
lj_edge_kernel_rep(const float* __restrict__ dist,
                   const int* __restrict__ atom_a,
                   const int* __restrict__ atom_b,
                   int n_edges) {
    int i = blockIdx.x * blockDim.x + threadIdx.x;
    if (i >= n_edges) return;

    float x = __ldcs(&dist[3 * i + 0]);
    float y = __ldcs(&dist[3 * i + 1]);
    float z = __ldcs(&dist[3 * i + 2]);
    float h = lj_half_e(x, y, z);

    int ia = __ldcs(&atom_a[i]);
    int ib = __ldcs(&atom_b[i]);

    float* rep = g_scratch + (i & (NREP - 1)) * REP_STRIDE;
    atomicAdd(rep + ia, h);   // RED.ADD, fire-and-forget
    atomicAdd(rep + ib, h);
}

// Reduce NREP replicas -> out, 1 atom/thread.
__global__ void __launch_bounds__(256)
lj_reduce_kernel_s(float* __restrict__ out, int n_atoms) {
    int i = blockIdx.x * blockDim.x + threadIdx.x;
    if (i >= n_atoms) return;

    float s = 0.0f;
    #pragma unroll
    for (int r = 0; r < NREP; r++)
        s += g_scratch[r * REP_STRIDE + i];
    out[i] = s;
}

// Fallback kernels (atom count exceeds static scratch): direct atomics.
__global__ void lj_zero_out(float* __restrict__ out, int n) {
    int i = blockIdx.x * blockDim.x + threadIdx.x;
    if (i < n) out[i] = 0.0f;
}
__global__ void lj_edge_kernel_direct(const float* __restrict__ dist,
                                      const int* __restrict__ atom_a,
                                      const int* __restrict__ atom_b,
                                      float* __restrict__ out,
                                      int n_edges) {
    int i = blockIdx.x * blockDim.x + threadIdx.x;
    if (i >= n_edges) return;
    float h = lj_half_e(dist[3*i], dist[3*i+1], dist[3*i+2]);
    atomicAdd(out + atom_a[i], h);
    atomicAdd(out + atom_b[i], h);
}

// Backup zero kernel in case symbol lookup ever fails.
__global__ void __launch_bounds__(256)
lj_zero_scratch_v4(int n_vec4) {
    int i = blockIdx.x * blockDim.x + threadIdx.x;
    if (i < n_vec4)
        reinterpret_cast<float4*>(g_scratch)[i] = make_float4(0.f, 0.f, 0.f, 0.f);
}

extern "C" void kernel_launch(void* const* d_in, const int* in_sizes, int n_in,
                              void* d_out, int out_size) {
    const float* dist   = (const float*)d_in[0];
    const int*   atom_a = (const int*)d_in[1];   // JAX x64-disabled: int32
    const int*   atom_b = (const int*)d_in[2];
    float* out = (float*)d_out;

    int n_edges = in_sizes[1];
    int n_atoms = out_size;
    const int T = 256;

    if (n_atoms <= MAX_ATOMS) {
        // Zero scratch via memset node (beats the latency-bound zero kernel).
        void* scratch_ptr = nullptr;
        cudaError_t e = cudaGetSymbolAddress(&scratch_ptr, g_scratch);
        if (e == cudaSuccess && scratch_ptr != nullptr) {
            cudaMemsetAsync(scratch_ptr, 0, sizeof(float) * NREP * REP_STRIDE, 0);
        } else {
            int n_vec4 = (NREP * REP_STRIDE) / 4;
            lj_zero_scratch_v4<<<(n_vec4 + T - 1) / T, T>>>(n_vec4);
        }

        lj_edge_kernel_rep<<<(n_edges + T - 1) / T, T>>>(dist, atom_a, atom_b, n_edges);
        lj_reduce_kernel_s<<<(n_atoms + T - 1) / T, T>>>(out, n_atoms);
    } else {
        lj_zero_out<<<(n_atoms + T - 1) / T, T>>>(out, n_atoms);
        lj_edge_kernel_direct<<<(n_edges + T - 1) / T, T>>>(dist, atom_a, atom_b, out, n_edges);
    }
}